// round 11
// baseline (speedup 1.0000x reference)
#include <cuda_runtime.h>
#include <cstdint>

#define BB 16
#define TT 2048
#define FF 512
#define HB (BB / 2)   // batches per half
#define SPB 4         // segments per k_pool block
#define GR 16         // rows per k_gate block (32KB smem)

// Scratch (allocation-free rule: device globals)
__device__ float g_wt[BB * TT];      // gate weights
__device__ int   g_vlist[BB * TT];   // packed valley positions per batch
__device__ int   g_nv[BB];           // number of valleys k per batch

__device__ __forceinline__ uint32_t smem_u32(const void* p) {
    uint32_t a;
    asm("{ .reg .u64 t; cvta.to.shared.u64 t, %1; cvt.u32.u64 %0, t; }"
        : "=r"(a) : "l"(p));
    return a;
}

// ---------------------------------------------------------------------------
// Kernel 1 (R6 proven, batch-half parameterized): wt = sigmoid(x·w + b).
// ONE cp.async.bulk (TMA) copies 16 rows (32KB) into smem; each warp dots
// 2 rows from smem against register-held w. row_base does ALL the offsetting.
// ---------------------------------------------------------------------------
__global__ void k_gate(const float* __restrict__ x,
                       const float* __restrict__ w,
                       const float* __restrict__ bias,
                       int row_base) {
    __shared__ alignas(16) float4 sx[GR * FF / 4];          // 32 KB
    __shared__ alignas(8)  unsigned long long mbar;

    int tid  = threadIdx.x;                                  // 256
    int lane = tid & 31;
    int wid  = tid >> 5;                                     // 8 warps

    const float4* wr = (const float4*)w;
    float4 c0 = wr[lane];
    float4 c1 = wr[lane + 32];
    float4 c2 = wr[lane + 64];
    float4 c3 = wr[lane + 96];
    float  bz = bias[0];

    uint32_t mb = smem_u32(&mbar);
    uint32_t ds = smem_u32(sx);
    const int BYTES = GR * FF * 4;                           // 32768

    if (tid == 0) {
        asm volatile("mbarrier.init.shared.b64 [%0], 1;" :: "r"(mb) : "memory");
    }
    __syncthreads();
    if (tid == 0) {
        const char* src = (const char*)x
            + ((size_t)row_base + (size_t)blockIdx.x * GR) * (FF * 4);
        asm volatile("mbarrier.arrive.expect_tx.shared.b64 _, [%0], %1;"
                     :: "r"(mb), "r"(BYTES) : "memory");
        asm volatile("cp.async.bulk.shared::cta.global.mbarrier::complete_tx::bytes "
                     "[%0], [%1], %2, [%3];"
                     :: "r"(ds), "l"(src), "r"(BYTES), "r"(mb) : "memory");
    }

    {
        uint32_t done;
        asm volatile(
            "{\n\t.reg .pred p;\n\t"
            "mbarrier.try_wait.parity.acquire.cta.shared::cta.b64 p, [%1], 0;\n\t"
            "selp.b32 %0, 1, 0, p;\n\t}"
            : "=r"(done) : "r"(mb) : "memory");
        if (!done) {
            asm volatile(
                "{\n\t.reg .pred P1;\n"
                "W%=:\n\t"
                "mbarrier.try_wait.parity.acquire.cta.shared::cta.b64 P1, [%0], 0, 0x989680;\n\t"
                "@P1 bra.uni D%=;\n\t"
                "bra.uni W%=;\n"
                "D%=:\n\t}"
                :: "r"(mb) : "memory");
        }
    }

    int r0 = wid * 2;
    const float4* row0 = sx + r0 * (FF / 4);
    const float4* row1 = row0 + (FF / 4);

    float s0 = 0.f, s1 = 0.f;
#pragma unroll
    for (int j = 0; j < 4; j++) {
        float4 cj = (j == 0) ? c0 : (j == 1) ? c1 : (j == 2) ? c2 : c3;
        float4 a0 = row0[lane + 32 * j];
        float4 a1 = row1[lane + 32 * j];
        s0 += a0.x * cj.x + a0.y * cj.y + a0.z * cj.z + a0.w * cj.w;
        s1 += a1.x * cj.x + a1.y * cj.y + a1.z * cj.z + a1.w * cj.w;
    }
#pragma unroll
    for (int o = 16; o; o >>= 1) {
        s0 += __shfl_down_sync(0xffffffffu, s0, o);
        s1 += __shfl_down_sync(0xffffffffu, s1, o);
    }
    if (lane == 0) {
        int r = row_base + blockIdx.x * GR + r0;
        float2 r2;
        r2.x = 1.f / (1.f + expf(-(s0 + bz)));
        r2.y = 1.f / (1.f + expf(-(s1 + bz)));
        *(float2*)(g_wt + r) = r2;
    }
}

// ---------------------------------------------------------------------------
// Kernel 2 (R6 proven): per batch, strict local minima of wt, left-packed.
// ---------------------------------------------------------------------------
__global__ void k_valleys(int b_base) {
    __shared__ float sw[TT];
    __shared__ int   wsum[9];

    int b    = b_base + blockIdx.x;
    int tid  = threadIdx.x;                // 256 threads
    int lane = tid & 31;
    int wid  = tid >> 5;

    for (int t = tid; t < TT; t += 256) sw[t] = g_wt[b * TT + t];
    __syncthreads();

    const int PER = TT / 256;
    int base = tid * PER;
    unsigned char fl[PER];
    int c = 0;
#pragma unroll
    for (int j = 0; j < PER; j++) {
        int   t   = base + j;
        float wtt = sw[t];
        float bef = (t == 0)      ? 0.f : sw[t - 1];
        float aft = (t == TT - 1) ? 0.f : sw[t + 1];
        bool  v   = (wtt < bef) && (wtt < aft);
        fl[j] = v ? 1 : 0;
        c += v ? 1 : 0;
    }

    int incl = c;
#pragma unroll
    for (int o = 1; o < 32; o <<= 1) {
        int v = __shfl_up_sync(0xffffffffu, incl, o);
        if (lane >= o) incl += v;
    }
    if (lane == 31) wsum[wid] = incl;
    __syncthreads();
    if (tid == 0) {
        int run = 0;
#pragma unroll
        for (int j = 0; j < 8; j++) { int t = wsum[j]; wsum[j] = run; run += t; }
        wsum[8] = run;
        g_nv[b] = run;
    }
    __syncthreads();

    int pos = wsum[wid] + incl - c;
#pragma unroll
    for (int j = 0; j < PER; j++) {
        if (fl[j]) g_vlist[b * TT + (pos++)] = base + j;
    }
}

// ---------------------------------------------------------------------------
// Kernel 3 (R6 proven, batch-half parameterized): streaming segment pooling.
// ---------------------------------------------------------------------------
__global__ void k_pool(const float* __restrict__ x,
                       float* __restrict__ out,
                       int b_base) {
    int b   = b_base + blockIdx.y;
    int j   = blockIdx.x;
    int tid = threadIdx.x;                 // 128
    int k = g_nv[b];
    int n = k + 1;
    int i0 = j * SPB;

    float4 z4 = make_float4(0.f, 0.f, 0.f, 0.f);
    for (int i = max(i0, n); i < i0 + SPB; i++)
        __stcs((float4*)(out + ((size_t)b * TT + i) * FF) + tid, z4);

    if (i0 < n) {
        int iEnd = min(i0 + SPB, n);
        const float4* xb = (const float4*)(x + (size_t)b * TT * FF);
        const float*  wb = g_wt + b * TT;
        const int*    vb = g_vlist + b * TT;

        float4 carry = z4;
        float  dcarry = 0.f;
        bool   have = false;

        for (int i = i0; i < iEnd; i++) {
            int S = (i == 0) ? 0 : vb[i - 1];
            int E = (i < k) ? min(vb[i] + 2, TT) : TT;

            float4 acc;
            float  den;
            int t;
            if (have) { acc = carry; den = dcarry; t = S + 2; }
            else      { acc = z4;    den = 0.f;    t = S;     }

            int bodyEnd = E - 2;
#pragma unroll 2
            for (; t < bodyEnd; t++) {
                float  wv = wb[t];
                float4 xv = xb[(size_t)t * (FF / 4) + tid];
                acc.x += wv * xv.x;  acc.y += wv * xv.y;
                acc.z += wv * xv.z;  acc.w += wv * xv.w;
                den += wv;
            }
            float4 c2 = z4;
            float  d2 = 0.f;
            for (; t < E; t++) {
                float  wv = wb[t];
                float4 xv = xb[(size_t)t * (FF / 4) + tid];
                acc.x += wv * xv.x;  acc.y += wv * xv.y;
                acc.z += wv * xv.z;  acc.w += wv * xv.w;
                den += wv;
                c2.x += wv * xv.x;  c2.y += wv * xv.y;
                c2.z += wv * xv.z;  c2.w += wv * xv.w;
                d2 += wv;
            }
            carry = c2; dcarry = d2; have = true;

            float inv = 1.f / fmaxf(den, 1e-6f);
            float4 r;
            r.x = acc.x * inv;  r.y = acc.y * inv;
            r.z = acc.z * inv;  r.w = acc.w * inv;
            __stcs((float4*)(out + ((size_t)b * TT + i) * FF) + tid, r);
        }
    }
}

// ---------------------------------------------------------------------------
// Kernel 4: new_mask (needs GLOBAL max over all batches' counts).
// ---------------------------------------------------------------------------
__global__ void k_mask(const int* __restrict__ seq_len,
                       float* __restrict__ out) {
    __shared__ int s_mc;
    int tid = threadIdx.x;                 // 256
    if (tid == 0) {
        int mc = 0;
#pragma unroll
        for (int bb = 0; bb < BB; bb++) {
            int c = g_nv[bb] + 1;
            if (c > mc) mc = c;
        }
        s_mc = mc;
    }
    __syncthreads();
    int g = blockIdx.x * 256 + tid;        // grid = BB*TT/256 = 128 blocks
    int b = g / TT;
    int i = g % TT;
    int len  = min(seq_len[b], TT);
    int len0 = min(seq_len[0], TT);
    int nl   = (int)((float)len / (float)len0 * (float)s_mc);
    float* m = out + (size_t)BB * TT * FF;
    __stcs(&m[g], (i < nl) ? 1.f : 0.f);
}

// ---------------------------------------------------------------------------
extern "C" void kernel_launch(void* const* d_in, const int* in_sizes, int n_in,
                              void* d_out, int out_size) {
    const float* x    = (const float*)d_in[0];   // [B,T,F] f32
    const float* w    = (const float*)d_in[1];   // [F,1]  f32
    const float* bias = (const float*)d_in[2];   // [1]    f32
    const int*   seq  = (const int*)d_in[3];     // [B]    i32
    float* out = (float*)d_out;

    int write_mask = (out_size >= BB * TT * FF + BB * TT) ? 1 : 0;

    const int gate_blocks_half = (HB * TT) / GR;             // 1024
    dim3 pool_grid(TT / SPB, HB);                            // 512 x 8

    cudaStream_t s2 = 0;
    cudaEvent_t evA = 0, evC = 0;
    bool forked =
        (cudaStreamCreateWithFlags(&s2, cudaStreamNonBlocking) == cudaSuccess) &&
        (cudaEventCreateWithFlags(&evA, cudaEventDisableTiming) == cudaSuccess) &&
        (cudaEventCreateWithFlags(&evC, cudaEventDisableTiming) == cudaSuccess);

    if (forked) {
        // main: gate(H1)
        k_gate<<<gate_blocks_half, 256>>>(x, w, bias, 0);
        cudaEventRecord(evA, 0);

        // fork: valleys(H1) + pool(H1) on s2, overlapping gate(H2)
        cudaStreamWaitEvent(s2, evA, 0);
        k_valleys<<<HB, 256, 0, s2>>>(0);
        k_pool<<<pool_grid, 128, 0, s2>>>(x, out, 0);
        cudaEventRecord(evC, s2);

        // main: gate(H2) -> valleys(H2) -> pool(H2)
        // NOTE: x passed UN-offset; row_base does the addressing (R10 bug fix).
        k_gate<<<gate_blocks_half, 256>>>(x, w, bias, HB * TT);
        k_valleys<<<HB, 256>>>(HB);
        k_pool<<<pool_grid, 128>>>(x, out, HB);

        // join s2, then global-max mask
        cudaStreamWaitEvent(0, evC, 0);
        if (write_mask)
            k_mask<<<(BB * TT) / 256, 256>>>(seq, out);
        // s2/evA/evC intentionally not destroyed (capture-referenced);
        // few host handles leak per process, harmless.
    } else {
        // sequential fallback (identical math)
        k_gate<<<gate_blocks_half, 256>>>(x, w, bias, 0);
        k_gate<<<gate_blocks_half, 256>>>(x, w, bias, HB * TT);
        k_valleys<<<HB, 256>>>(0);
        k_valleys<<<HB, 256>>>(HB);
        k_pool<<<pool_grid, 128>>>(x, out, 0);
        k_pool<<<pool_grid, 128>>>(x, out, HB);
        if (write_mask)
            k_mask<<<(BB * TT) / 256, 256>>>(seq, out);
    }
}

// round 12
// speedup vs baseline: 1.0515x; 1.0515x over previous
#include <cuda_runtime.h>
#include <cstdint>

#define BB 16
#define TT 2048
#define FF 512
#define SPB 4      // segments per k_pool block
#define GR 16      // rows per k_gate block (32KB smem); 128 blocks per batch

// Scratch (allocation-free rule: device globals)
__device__ float g_wt[BB * TT];      // gate weights
__device__ int   g_vlist[BB * TT];   // packed valley positions per batch
__device__ int   g_nv[BB];           // number of valleys k per batch
__device__ int   g_done[BB];         // finished-block counters (self-resetting)

__device__ __forceinline__ uint32_t smem_u32(const void* p) {
    uint32_t a;
    asm("{ .reg .u64 t; cvta.to.shared.u64 t, %1; cvt.u32.u64 %0, t; }"
        : "=r"(a) : "l"(p));
    return a;
}

// ---------------------------------------------------------------------------
// Kernel 1: wt = sigmoid(x·w + b), R6-proven one-shot TMA block structure,
// PLUS fused valley detection: the last gate block to finish a batch (128
// blocks/batch) runs that batch's valley scan in its smem buffer.
// ---------------------------------------------------------------------------
__global__ void k_gate(const float* __restrict__ x,
                       const float* __restrict__ w,
                       const float* __restrict__ bias) {
    __shared__ alignas(16) float4 sx[GR * FF / 4];          // 32 KB
    __shared__ alignas(8)  unsigned long long mbar;
    __shared__ int s_win;
    __shared__ int wsum[9];

    int tid  = threadIdx.x;                                  // 256
    int lane = tid & 31;
    int wid  = tid >> 5;                                     // 8 warps

    const float4* wr = (const float4*)w;
    float4 c0 = wr[lane];
    float4 c1 = wr[lane + 32];
    float4 c2 = wr[lane + 64];
    float4 c3 = wr[lane + 96];
    float  bz = bias[0];

    uint32_t mb = smem_u32(&mbar);
    uint32_t ds = smem_u32(sx);
    const int BYTES = GR * FF * 4;                           // 32768

    if (tid == 0) {
        asm volatile("mbarrier.init.shared.b64 [%0], 1;" :: "r"(mb) : "memory");
    }
    __syncthreads();
    if (tid == 0) {
        const char* src = (const char*)x + (size_t)blockIdx.x * BYTES;
        asm volatile("mbarrier.arrive.expect_tx.shared.b64 _, [%0], %1;"
                     :: "r"(mb), "r"(BYTES) : "memory");
        asm volatile("cp.async.bulk.shared::cta.global.mbarrier::complete_tx::bytes "
                     "[%0], [%1], %2, [%3];"
                     :: "r"(ds), "l"(src), "r"(BYTES), "r"(mb) : "memory");
    }

    {
        uint32_t done;
        asm volatile(
            "{\n\t.reg .pred p;\n\t"
            "mbarrier.try_wait.parity.acquire.cta.shared::cta.b64 p, [%1], 0;\n\t"
            "selp.b32 %0, 1, 0, p;\n\t}"
            : "=r"(done) : "r"(mb) : "memory");
        if (!done) {
            asm volatile(
                "{\n\t.reg .pred P1;\n"
                "W%=:\n\t"
                "mbarrier.try_wait.parity.acquire.cta.shared::cta.b64 P1, [%0], 0, 0x989680;\n\t"
                "@P1 bra.uni D%=;\n\t"
                "bra.uni W%=;\n"
                "D%=:\n\t}"
                :: "r"(mb) : "memory");
        }
    }

    int r0 = wid * 2;
    const float4* row0 = sx + r0 * (FF / 4);
    const float4* row1 = row0 + (FF / 4);

    float s0 = 0.f, s1 = 0.f;
#pragma unroll
    for (int j = 0; j < 4; j++) {
        float4 cj = (j == 0) ? c0 : (j == 1) ? c1 : (j == 2) ? c2 : c3;
        float4 a0 = row0[lane + 32 * j];
        float4 a1 = row1[lane + 32 * j];
        s0 += a0.x * cj.x + a0.y * cj.y + a0.z * cj.z + a0.w * cj.w;
        s1 += a1.x * cj.x + a1.y * cj.y + a1.z * cj.z + a1.w * cj.w;
    }
#pragma unroll
    for (int o = 16; o; o >>= 1) {
        s0 += __shfl_down_sync(0xffffffffu, s0, o);
        s1 += __shfl_down_sync(0xffffffffu, s1, o);
    }
    if (lane == 0) {
        int r = blockIdx.x * GR + r0;
        float2 r2;
        r2.x = 1.f / (1.f + expf(-(s0 + bz)));
        r2.y = 1.f / (1.f + expf(-(s1 + bz)));
        *(float2*)(g_wt + r) = r2;
    }
    __syncthreads();

    // ---- fused valley tail: last finished block of this batch scans it ----
    if (tid == 0) {
        __threadfence();                     // release our g_wt stores
        int b = blockIdx.x >> 7;             // 128 blocks per batch
        int old = atomicAdd(&g_done[b], 1);
        if (old == (TT / GR) - 1) {
            __threadfence();                 // acquire others' g_wt stores
            s_win = b;
        } else {
            s_win = -1;
        }
    }
    __syncthreads();
    int wb = s_win;
    if (wb < 0) return;

    // valley scan for batch wb (reuse sx as 8KB scratch; TMA long done)
    float* sw = (float*)sx;
    for (int t = tid; t < TT; t += 256) sw[t] = g_wt[wb * TT + t];
    __syncthreads();

    const int PER = TT / 256;                // 8
    int base = tid * PER;
    unsigned char fl[PER];
    int c = 0;
#pragma unroll
    for (int j = 0; j < PER; j++) {
        int   t   = base + j;
        float wtt = sw[t];
        float bef = (t == 0)      ? 0.f : sw[t - 1];
        float aft = (t == TT - 1) ? 0.f : sw[t + 1];
        bool  v   = (wtt < bef) && (wtt < aft);
        fl[j] = v ? 1 : 0;
        c += v ? 1 : 0;
    }
    int incl = c;
#pragma unroll
    for (int o = 1; o < 32; o <<= 1) {
        int v = __shfl_up_sync(0xffffffffu, incl, o);
        if (lane >= o) incl += v;
    }
    if (lane == 31) wsum[wid] = incl;
    __syncthreads();
    if (tid == 0) {
        int run = 0;
#pragma unroll
        for (int j = 0; j < 8; j++) { int t = wsum[j]; wsum[j] = run; run += t; }
        g_nv[wb] = run;
        g_done[wb] = 0;                      // reset for next graph replay
    }
    __syncthreads();
    int pos = wsum[wid] + incl - c;
#pragma unroll
    for (int j = 0; j < PER; j++) {
        if (fl[j]) g_vlist[wb * TT + (pos++)] = base + j;
    }
}

// ---------------------------------------------------------------------------
// Kernel 2 (R6 proven): streaming segment pooling; SPB segments per block,
// each x row read once, 2-row overlap carried in registers (ascending sum
// order preserved). Streaming stores keep x resident in L2. Also writes the
// new_mask row slice (global max over g_nv — all valleys done by now).
// ---------------------------------------------------------------------------
__global__ void k_pool(const float* __restrict__ x,
                       const int* __restrict__ seq_len,
                       float* __restrict__ out,
                       int write_mask) {
    int b   = blockIdx.y;
    int j   = blockIdx.x;
    int tid = threadIdx.x;                 // 128
    int k = g_nv[b];
    int n = k + 1;
    int i0 = j * SPB;

    float4 z4 = make_float4(0.f, 0.f, 0.f, 0.f);
    for (int i = max(i0, n); i < i0 + SPB; i++)
        __stcs((float4*)(out + ((size_t)b * TT + i) * FF) + tid, z4);

    if (i0 < n) {
        int iEnd = min(i0 + SPB, n);
        const float4* xb = (const float4*)(x + (size_t)b * TT * FF);
        const float*  wb = g_wt + b * TT;
        const int*    vb = g_vlist + b * TT;

        float4 carry = z4;
        float  dcarry = 0.f;
        bool   have = false;

        for (int i = i0; i < iEnd; i++) {
            int S = (i == 0) ? 0 : vb[i - 1];
            int E = (i < k) ? min(vb[i] + 2, TT) : TT;

            float4 acc;
            float  den;
            int t;
            if (have) { acc = carry; den = dcarry; t = S + 2; }
            else      { acc = z4;    den = 0.f;    t = S;     }

            int bodyEnd = E - 2;
#pragma unroll 2
            for (; t < bodyEnd; t++) {
                float  wv = wb[t];
                float4 xv = xb[(size_t)t * (FF / 4) + tid];
                acc.x += wv * xv.x;  acc.y += wv * xv.y;
                acc.z += wv * xv.z;  acc.w += wv * xv.w;
                den += wv;
            }
            float4 c2 = z4;
            float  d2 = 0.f;
            for (; t < E; t++) {
                float  wv = wb[t];
                float4 xv = xb[(size_t)t * (FF / 4) + tid];
                acc.x += wv * xv.x;  acc.y += wv * xv.y;
                acc.z += wv * xv.z;  acc.w += wv * xv.w;
                den += wv;
                c2.x += wv * xv.x;  c2.y += wv * xv.y;
                c2.z += wv * xv.z;  c2.w += wv * xv.w;
                d2 += wv;
            }
            carry = c2; dcarry = d2; have = true;

            float inv = 1.f / fmaxf(den, 1e-6f);
            float4 r;
            r.x = acc.x * inv;  r.y = acc.y * inv;
            r.z = acc.z * inv;  r.w = acc.w * inv;
            __stcs((float4*)(out + ((size_t)b * TT + i) * FF) + tid, r);
        }
    }

    if (write_mask && tid < SPB) {
        int i = i0 + tid;
        int mc = 0;
#pragma unroll
        for (int bb = 0; bb < BB; bb++) {
            int c = g_nv[bb] + 1;
            if (c > mc) mc = c;
        }
        int len  = min(seq_len[b], TT);
        int len0 = min(seq_len[0], TT);
        int nl   = (int)((float)len / (float)len0 * (float)mc);
        float* m = out + (size_t)BB * TT * FF;
        __stcs(&m[(size_t)b * TT + i], (i < nl) ? 1.f : 0.f);
    }
}

// ---------------------------------------------------------------------------
extern "C" void kernel_launch(void* const* d_in, const int* in_sizes, int n_in,
                              void* d_out, int out_size) {
    const float* x    = (const float*)d_in[0];   // [B,T,F] f32
    const float* w    = (const float*)d_in[1];   // [F,1]  f32
    const float* bias = (const float*)d_in[2];   // [1]    f32
    const int*   seq  = (const int*)d_in[3];     // [B]    i32
    float* out = (float*)d_out;

    int write_mask = (out_size >= BB * TT * FF + BB * TT) ? 1 : 0;

    k_gate<<<(BB * TT) / GR, 256>>>(x, w, bias);   // 2048 blocks, fused valleys
    dim3 grid(TT / SPB, BB);
    k_pool<<<grid, 128>>>(x, seq, out, write_mask);
}

// round 13
// speedup vs baseline: 1.1153x; 1.0607x over previous
#include <cuda_runtime.h>
#include <cstdint>

#define BB 16
#define TT 2048
#define FF 512
#define SPB 8      // segments per k_pool block
#define GR 16      // rows per k_gate block (32KB smem)

// Scratch (allocation-free rule: device globals)
__device__ float g_wt[BB * TT];      // gate weights
__device__ int   g_vlist[BB * TT];   // packed valley positions per batch
__device__ int   g_nv[BB];           // number of valleys k per batch

__device__ __forceinline__ uint32_t smem_u32(const void* p) {
    uint32_t a;
    asm("{ .reg .u64 t; cvta.to.shared.u64 t, %1; cvt.u32.u64 %0, t; }"
        : "=r"(a) : "l"(p));
    return a;
}

// ---------------------------------------------------------------------------
// Kernel 1 (R6 champion, verbatim): wt = sigmoid(x·w + b).
// ONE cp.async.bulk (TMA) copies 16 rows (32KB) into smem; each warp dots
// 2 rows from smem against register-held w.
// ---------------------------------------------------------------------------
__global__ void k_gate(const float* __restrict__ x,
                       const float* __restrict__ w,
                       const float* __restrict__ bias) {
    __shared__ alignas(16) float4 sx[GR * FF / 4];          // 32 KB
    __shared__ alignas(8)  unsigned long long mbar;

    int tid  = threadIdx.x;                                  // 256
    int lane = tid & 31;
    int wid  = tid >> 5;                                     // 8 warps

    const float4* wr = (const float4*)w;
    float4 c0 = wr[lane];
    float4 c1 = wr[lane + 32];
    float4 c2 = wr[lane + 64];
    float4 c3 = wr[lane + 96];
    float  bz = bias[0];

    uint32_t mb = smem_u32(&mbar);
    uint32_t ds = smem_u32(sx);
    const int BYTES = GR * FF * 4;                           // 32768

    if (tid == 0) {
        asm volatile("mbarrier.init.shared.b64 [%0], 1;" :: "r"(mb) : "memory");
    }
    __syncthreads();
    if (tid == 0) {
        const char* src = (const char*)x + (size_t)blockIdx.x * BYTES;
        asm volatile("mbarrier.arrive.expect_tx.shared.b64 _, [%0], %1;"
                     :: "r"(mb), "r"(BYTES) : "memory");
        asm volatile("cp.async.bulk.shared::cta.global.mbarrier::complete_tx::bytes "
                     "[%0], [%1], %2, [%3];"
                     :: "r"(ds), "l"(src), "r"(BYTES), "r"(mb) : "memory");
    }

    {
        uint32_t done;
        asm volatile(
            "{\n\t.reg .pred p;\n\t"
            "mbarrier.try_wait.parity.acquire.cta.shared::cta.b64 p, [%1], 0;\n\t"
            "selp.b32 %0, 1, 0, p;\n\t}"
            : "=r"(done) : "r"(mb) : "memory");
        if (!done) {
            asm volatile(
                "{\n\t.reg .pred P1;\n"
                "W%=:\n\t"
                "mbarrier.try_wait.parity.acquire.cta.shared::cta.b64 P1, [%0], 0, 0x989680;\n\t"
                "@P1 bra.uni D%=;\n\t"
                "bra.uni W%=;\n"
                "D%=:\n\t}"
                :: "r"(mb) : "memory");
        }
    }

    int r0 = wid * 2;
    const float4* row0 = sx + r0 * (FF / 4);
    const float4* row1 = row0 + (FF / 4);

    float s0 = 0.f, s1 = 0.f;
#pragma unroll
    for (int j = 0; j < 4; j++) {
        float4 cj = (j == 0) ? c0 : (j == 1) ? c1 : (j == 2) ? c2 : c3;
        float4 a0 = row0[lane + 32 * j];
        float4 a1 = row1[lane + 32 * j];
        s0 += a0.x * cj.x + a0.y * cj.y + a0.z * cj.z + a0.w * cj.w;
        s1 += a1.x * cj.x + a1.y * cj.y + a1.z * cj.z + a1.w * cj.w;
    }
#pragma unroll
    for (int o = 16; o; o >>= 1) {
        s0 += __shfl_down_sync(0xffffffffu, s0, o);
        s1 += __shfl_down_sync(0xffffffffu, s1, o);
    }
    if (lane == 0) {
        int r = blockIdx.x * GR + r0;
        float2 r2;
        r2.x = 1.f / (1.f + expf(-(s0 + bz)));
        r2.y = 1.f / (1.f + expf(-(s1 + bz)));
        *(float2*)(g_wt + r) = r2;
    }
}

// ---------------------------------------------------------------------------
// Kernel 2: per batch, strict local minima of wt, left-packed positions.
// 1024 threads, PER=2 -> minimal serial depth in this latency-bound kernel.
// ---------------------------------------------------------------------------
__global__ void k_valleys() {
    __shared__ float sw[TT];
    __shared__ int   wsum[32];

    int b    = blockIdx.x;
    int tid  = threadIdx.x;                // 1024 threads
    int lane = tid & 31;
    int wid  = tid >> 5;                   // 32 warps

    for (int t = tid; t < TT; t += 1024) sw[t] = g_wt[b * TT + t];
    __syncthreads();

    const int PER = TT / 1024;             // 2 consecutive t per thread
    int base = tid * PER;
    unsigned char fl[PER];
    int c = 0;
#pragma unroll
    for (int j = 0; j < PER; j++) {
        int   t   = base + j;
        float wtt = sw[t];
        float bef = (t == 0)      ? 0.f : sw[t - 1];
        float aft = (t == TT - 1) ? 0.f : sw[t + 1];
        bool  v   = (wtt < bef) && (wtt < aft);
        fl[j] = v ? 1 : 0;
        c += v ? 1 : 0;
    }

    int incl = c;
#pragma unroll
    for (int o = 1; o < 32; o <<= 1) {
        int v = __shfl_up_sync(0xffffffffu, incl, o);
        if (lane >= o) incl += v;
    }
    if (lane == 31) wsum[wid] = incl;
    __syncthreads();
    if (tid == 0) {
        int run = 0;
#pragma unroll
        for (int j = 0; j < 32; j++) { int t = wsum[j]; wsum[j] = run; run += t; }
        g_nv[b] = run;
    }
    __syncthreads();

    int pos = wsum[wid] + incl - c;
#pragma unroll
    for (int j = 0; j < PER; j++) {
        if (fl[j]) g_vlist[b * TT + (pos++)] = base + j;
    }
}

// ---------------------------------------------------------------------------
// Kernel 3 (R6 structure, SPB=8): streaming segment pooling; SPB consecutive
// segments per block, each x row read once, 2-row overlap carried in regs
// (ascending sum order preserved). Streaming stores keep x resident in L2.
// Also writes the new_mask row slice.
// ---------------------------------------------------------------------------
__global__ void k_pool(const float* __restrict__ x,
                       const int* __restrict__ seq_len,
                       float* __restrict__ out,
                       int write_mask) {
    int b   = blockIdx.y;
    int j   = blockIdx.x;
    int tid = threadIdx.x;                 // 128
    int k = g_nv[b];
    int n = k + 1;
    int i0 = j * SPB;

    float4 z4 = make_float4(0.f, 0.f, 0.f, 0.f);
    for (int i = max(i0, n); i < i0 + SPB; i++)
        __stcs((float4*)(out + ((size_t)b * TT + i) * FF) + tid, z4);

    if (i0 < n) {
        int iEnd = min(i0 + SPB, n);
        const float4* xb = (const float4*)(x + (size_t)b * TT * FF);
        const float*  wb = g_wt + b * TT;
        const int*    vb = g_vlist + b * TT;

        float4 carry = z4;
        float  dcarry = 0.f;
        bool   have = false;

        for (int i = i0; i < iEnd; i++) {
            int S = (i == 0) ? 0 : vb[i - 1];
            int E = (i < k) ? min(vb[i] + 2, TT) : TT;

            float4 acc;
            float  den;
            int t;
            if (have) { acc = carry; den = dcarry; t = S + 2; }
            else      { acc = z4;    den = 0.f;    t = S;     }

            int bodyEnd = E - 2;
#pragma unroll 2
            for (; t < bodyEnd; t++) {
                float  wv = wb[t];
                float4 xv = xb[(size_t)t * (FF / 4) + tid];
                acc.x += wv * xv.x;  acc.y += wv * xv.y;
                acc.z += wv * xv.z;  acc.w += wv * xv.w;
                den += wv;
            }
            float4 c2 = z4;
            float  d2 = 0.f;
            for (; t < E; t++) {
                float  wv = wb[t];
                float4 xv = xb[(size_t)t * (FF / 4) + tid];
                acc.x += wv * xv.x;  acc.y += wv * xv.y;
                acc.z += wv * xv.z;  acc.w += wv * xv.w;
                den += wv;
                c2.x += wv * xv.x;  c2.y += wv * xv.y;
                c2.z += wv * xv.z;  c2.w += wv * xv.w;
                d2 += wv;
            }
            carry = c2; dcarry = d2; have = true;

            float inv = 1.f / fmaxf(den, 1e-6f);
            float4 r;
            r.x = acc.x * inv;  r.y = acc.y * inv;
            r.z = acc.z * inv;  r.w = acc.w * inv;
            __stcs((float4*)(out + ((size_t)b * TT + i) * FF) + tid, r);
        }
    }

    if (write_mask && tid < SPB) {
        int i = i0 + tid;
        int mc = 0;
#pragma unroll
        for (int bb = 0; bb < BB; bb++) {
            int c = g_nv[bb] + 1;
            if (c > mc) mc = c;
        }
        int len  = min(seq_len[b], TT);
        int len0 = min(seq_len[0], TT);
        int nl   = (int)((float)len / (float)len0 * (float)mc);
        float* m = out + (size_t)BB * TT * FF;
        __stcs(&m[(size_t)b * TT + i], (i < nl) ? 1.f : 0.f);
    }
}

// ---------------------------------------------------------------------------
extern "C" void kernel_launch(void* const* d_in, const int* in_sizes, int n_in,
                              void* d_out, int out_size) {
    const float* x    = (const float*)d_in[0];   // [B,T,F] f32
    const float* w    = (const float*)d_in[1];   // [F,1]  f32
    const float* bias = (const float*)d_in[2];   // [1]    f32
    const int*   seq  = (const int*)d_in[3];     // [B]    i32
    float* out = (float*)d_out;

    int write_mask = (out_size >= BB * TT * FF + BB * TT) ? 1 : 0;

    k_gate<<<(BB * TT) / GR, 256>>>(x, w, bias);   // 2048 blocks, TMA
    k_valleys<<<BB, 1024>>>();
    dim3 grid(TT / SPB, BB);                       // 256 x 16 blocks
    k_pool<<<grid, 128>>>(x, seq, out, write_mask);
}